// round 8
// baseline (speedup 1.0000x reference)
#include <cuda_runtime.h>
#include <cuda_fp16.h>

#define H    32
#define NMAX 100000
#define EMAX 3200000
#define PMAX (EMAX + 4 * NMAX)
#define NL   3

// ---- scratch (static; no allocation allowed) ----
__device__ __half d_Th[NMAX * H];      // T = node_in @ W_msg[:34]  (fp16)
__device__ float  d_h[NMAX * H];       // hidden state
__device__ float  d_pool[H];           // column sums of h
__device__ float  d_g[H];              // global supernode state
__device__ int    d_cnt[NMAX];         // degree -> scatter cursor
__device__ int    d_tmp[NMAX];         // block-local inclusive scan (padded)
__device__ int    d_rowptr[NMAX + 1];  // padded CSR row pointers (by receiver)
__device__ int    d_bsum[1024];
__device__ int    d_boff[1024];
__device__ __align__(16) float2 d_pay[PMAX];  // {sender_bits, mask}; pad slots stay 0
__device__ float4 d_aef[NMAX];         // sum mask*EF per receiver
__device__ unsigned d_ticket;          // last-block-done counter

// ---------------------------------------------------------------------------
// init: V=(1,0) ; h = PQ @ W_in + b_in ; T0 = [1,0,h] @ W_msg[0][:34]
// ---------------------------------------------------------------------------
__global__ void init_kernel(const float* __restrict__ PQ,
                            const float* __restrict__ Win,
                            const float* __restrict__ bin,
                            const float* __restrict__ Wmsg0,
                            float* __restrict__ V, int N) {
    __shared__ float Ws[34 * H];
    __shared__ float hs[8][H];
    for (int t = threadIdx.x; t < 34 * H; t += blockDim.x) Ws[t] = Wmsg0[t];

    int gid = blockIdx.x * blockDim.x + threadIdx.x;
    if (gid < H) { d_g[gid] = 0.f; d_pool[gid] = 0.f; }
    if (gid == 0) d_ticket = 0u;
    if (gid < N) {
        d_cnt[gid] = 0;
        d_aef[gid] = make_float4(0.f, 0.f, 0.f, 0.f);
    }
    if (gid < N * 2) V[gid] = (gid & 1) ? 0.f : 1.f;

    bool active = gid < N * H;
    int i = gid >> 5, j = gid & 31, w = threadIdx.x >> 5;
    float h = 0.f;
    if (active) {
        float p = __ldg(&PQ[i * 2]);
        float q = __ldg(&PQ[i * 2 + 1]);
        h = p * __ldg(&Win[j]) + q * __ldg(&Win[H + j]) + __ldg(&bin[j]);
        hs[w][j] = h;
    }
    __syncthreads();
    if (active) {
        d_h[gid] = h;
        float acc = Ws[j];                 // V = (1, 0)
#pragma unroll
        for (int k = 0; k < H; k++) acc += hs[w][k] * Ws[(2 + k) * H + j];
        d_Th[gid] = __float2half_rn(acc);
    }
}

// ---------------------------------------------------------------------------
// CSR build: histogram -> scan (padded to 4) -> scatter(+AEF)
// ---------------------------------------------------------------------------
__global__ void hist_kernel(const int* __restrict__ recv, int E) {
    int e = blockIdx.x * blockDim.x + threadIdx.x;
    if (e < E) atomicAdd(&d_cnt[__ldg(&recv[e])], 1);
}

__global__ void scan1_kernel(int N) {
    __shared__ int ws[32];
    int tid = threadIdx.x, lane = tid & 31, wid = tid >> 5;
    int i = blockIdx.x * 1024 + tid;
    int v = (i < N) ? ((d_cnt[i] + 3) & ~3) : 0;   // padded degree
    int s = v;
#pragma unroll
    for (int off = 1; off < 32; off <<= 1) {
        int n = __shfl_up_sync(0xffffffffu, s, off);
        if (lane >= off) s += n;
    }
    if (lane == 31) ws[wid] = s;
    __syncthreads();
    if (wid == 0) {
        int t = ws[lane];
#pragma unroll
        for (int off = 1; off < 32; off <<= 1) {
            int n = __shfl_up_sync(0xffffffffu, t, off);
            if (lane >= off) t += n;
        }
        ws[lane] = t;
    }
    __syncthreads();
    if (wid > 0) s += ws[wid - 1];
    if (i < N) d_tmp[i] = s;
    if (tid == 1023) d_bsum[blockIdx.x] = s;
}

__global__ void scan2_kernel(int nb) {
    __shared__ int ws[32];
    int tid = threadIdx.x, lane = tid & 31, wid = tid >> 5;
    int v = (tid < nb) ? d_bsum[tid] : 0;
    int s = v;
#pragma unroll
    for (int off = 1; off < 32; off <<= 1) {
        int n = __shfl_up_sync(0xffffffffu, s, off);
        if (lane >= off) s += n;
    }
    if (lane == 31) ws[wid] = s;
    __syncthreads();
    if (wid == 0) {
        int t = ws[lane];
#pragma unroll
        for (int off = 1; off < 32; off <<= 1) {
            int n = __shfl_up_sync(0xffffffffu, t, off);
            if (lane >= off) t += n;
        }
        ws[lane] = t;
    }
    __syncthreads();
    if (wid > 0) s += ws[wid - 1];
    d_boff[tid] = s - v;   // exclusive
}

__global__ void scan3_kernel(int N) {
    int i = blockIdx.x * blockDim.x + threadIdx.x;
    if (i == 0) d_rowptr[0] = 0;
    if (i >= N) return;
    int real = d_cnt[i];
    int pad  = (real + 3) & ~3;
    int incl = d_tmp[i] + d_boff[i >> 10];  // inclusive padded prefix
    d_rowptr[i + 1] = incl;
    d_cnt[i] = incl - pad;                  // start cursor
}

__global__ void scatter_kernel(const int*   __restrict__ send,
                               const int*   __restrict__ recv,
                               const float* __restrict__ ef,
                               const float* __restrict__ mask, int E) {
    int e = blockIdx.x * blockDim.x + threadIdx.x;
    if (e >= E) return;
    int r = __ldg(&recv[e]);
    int pos = atomicAdd(&d_cnt[r], 1);
    float mk = __ldg(&mask[e]);
    d_pay[pos] = make_float2(__int_as_float(__ldg(&send[e])), mk);
    float4 f = __ldg((const float4*)ef + e);
    float4* dst = &d_aef[r];
    asm volatile("red.global.add.v4.f32 [%0], {%1,%2,%3,%4};"
                 :: "l"(dst), "f"(mk * f.x), "f"(mk * f.y),
                    "f"(mk * f.z), "f"(mk * f.w) : "memory");
}

// ---------------------------------------------------------------------------
// agg: h[r] = relu( sum mask*T[s] + AEF[r]@W_ef + (sum mask)*b ) ; pool colsums;
// last block computes g = relu([g, pool/N] @ Wg + bg) and resets pool/ticket.
// Warp per node: subgroup (lane>>3) owns one of 4 edges, cols = (lane&7)*4.
// ---------------------------------------------------------------------------
__global__ void __launch_bounds__(256)
agg_kernel(const float* __restrict__ Wmsg, const float* __restrict__ bmsg,
           const float* __restrict__ Wg, const float* __restrict__ bg,
           float invN, int N, int totalWarps, int numBlocks) {
    __shared__ float4 wsum[8][8];
    __shared__ float  gin[2 * H];
    __shared__ bool   sLast;

    int lane = threadIdx.x & 31;
    int warp = threadIdx.x >> 5;
    int sub  = lane >> 3;
    int col  = (lane & 7) * 4;
    bool hi  = sub & 2;
    bool odd = sub & 1;

    float4 w0 = *(const float4*)&Wmsg[34 * H + col];
    float4 w1 = *(const float4*)&Wmsg[35 * H + col];
    float4 w2 = *(const float4*)&Wmsg[36 * H + col];
    float4 w3 = *(const float4*)&Wmsg[37 * H + col];
    float4 bb = *(const float4*)&bmsg[col];

    float4 colsum = make_float4(0.f, 0.f, 0.f, 0.f);

    for (int node = blockIdx.x * 8 + warp; node < N; node += totalWarps) {
        int beg = __ldg(&d_rowptr[node]), end = __ldg(&d_rowptr[node + 1]);
        float4 acc = make_float4(0.f, 0.f, 0.f, 0.f);
        float  cnt = 0.f;
        for (int k = beg; k < end; k += 4) {
            float4 pA = *(const float4*)&d_pay[k];      // edges k, k+1 (broadcast)
            float4 pB = *(const float4*)&d_pay[k + 2];  // edges k+2, k+3
            float sb = hi ? (odd ? pB.z : pB.x) : (odd ? pA.z : pA.x);
            float mk = hi ? (odd ? pB.w : pB.y) : (odd ? pA.w : pA.y);
            uint2 r = *(const uint2*)(d_Th + __float_as_int(sb) * H + col);
            float2 lo  = __half22float2(*(__half2*)&r.x);
            float2 hi2 = __half22float2(*(__half2*)&r.y);
            acc.x = fmaf(mk, lo.x,  acc.x); acc.y = fmaf(mk, lo.y,  acc.y);
            acc.z = fmaf(mk, hi2.x, acc.z); acc.w = fmaf(mk, hi2.y, acc.w);
            cnt += mk;
        }
        // reduce the 4 subgroups (same col, different edge slots)
#pragma unroll
        for (int off = 8; off <= 16; off <<= 1) {
            acc.x += __shfl_xor_sync(0xffffffffu, acc.x, off);
            acc.y += __shfl_xor_sync(0xffffffffu, acc.y, off);
            acc.z += __shfl_xor_sync(0xffffffffu, acc.z, off);
            acc.w += __shfl_xor_sync(0xffffffffu, acc.w, off);
            cnt   += __shfl_xor_sync(0xffffffffu, cnt, off);
        }
        if (sub == 0) {   // lanes 0-7 finalize + store the fp32 row
            float4 aef = d_aef[node];
            acc.x += aef.x * w0.x + aef.y * w1.x + aef.z * w2.x + aef.w * w3.x + cnt * bb.x;
            acc.y += aef.x * w0.y + aef.y * w1.y + aef.z * w2.y + aef.w * w3.y + cnt * bb.y;
            acc.z += aef.x * w0.z + aef.y * w1.z + aef.z * w2.z + aef.w * w3.z + cnt * bb.z;
            acc.w += aef.x * w0.w + aef.y * w1.w + aef.z * w2.w + aef.w * w3.w + cnt * bb.w;
            acc.x = fmaxf(acc.x, 0.f); acc.y = fmaxf(acc.y, 0.f);
            acc.z = fmaxf(acc.z, 0.f); acc.w = fmaxf(acc.w, 0.f);
            *(float4*)&d_h[node * H + col] = acc;
            colsum.x += acc.x; colsum.y += acc.y;
            colsum.z += acc.z; colsum.w += acc.w;
        }
    }

    if (lane < 8) wsum[warp][lane] = colsum;
    __syncthreads();
    if (threadIdx.x < 8) {
        float4 s = make_float4(0.f, 0.f, 0.f, 0.f);
#pragma unroll
        for (int w = 0; w < 8; w++) {
            float4 v = wsum[w][threadIdx.x];
            s.x += v.x; s.y += v.y; s.z += v.z; s.w += v.w;
        }
        float* dst = &d_pool[threadIdx.x * 4];
        asm volatile("red.global.add.v4.f32 [%0], {%1,%2,%3,%4};"
                     :: "l"(dst), "f"(s.x), "f"(s.y), "f"(s.z), "f"(s.w) : "memory");
        __threadfence();   // writer-side fence before ticket
    }
    __syncthreads();
    if (threadIdx.x == 0) {
        unsigned t = atomicAdd(&d_ticket, 1u);
        sLast = (t == (unsigned)(numBlocks - 1));
    }
    __syncthreads();
    if (sLast && threadIdx.x < H) {
        __threadfence();   // reader-side fence: all pool reds now visible
        int t = threadIdx.x;
        gin[t]     = d_g[t];
        gin[H + t] = d_pool[t] * invN;
        __syncwarp();
        float acc = __ldg(&bg[t]);
#pragma unroll
        for (int k = 0; k < 2 * H; k++) acc += gin[k] * __ldg(&Wg[k * H + t]);
        d_g[t]    = fmaxf(acc, 0.f);
        d_pool[t] = 0.f;
        if (t == 0) d_ticket = 0u;
    }
}

// ---------------------------------------------------------------------------
// node update: u = relu([h, g] @ W_n + b_n) ; V += u @ W_out + b_out ; h = u ;
// then T_next = [Vnew, u] @ W_msg[l+1][:34]   (fused next-layer prep)
// ---------------------------------------------------------------------------
__global__ void __launch_bounds__(1024)
node_kernel(const float* __restrict__ Wn, const float* __restrict__ bn,
            const float* __restrict__ Wout, const float* __restrict__ bout,
            const float* __restrict__ WmsgNext,   // nullptr on last layer
            float* __restrict__ V, int N) {
    __shared__ float Ws[2 * H * H];
    __shared__ float Wm[34 * H];
    __shared__ float gs[H];
    __shared__ float hs[32][H];
    for (int t = threadIdx.x; t < 2 * H * H; t += blockDim.x) Ws[t] = Wn[t];
    if (WmsgNext)
        for (int t = threadIdx.x; t < 34 * H; t += blockDim.x) Wm[t] = WmsgNext[t];
    if (threadIdx.x < H) gs[threadIdx.x] = d_g[threadIdx.x];
    __syncthreads();

    int w = threadIdx.x >> 5, j = threadIdx.x & 31;
    int i = blockIdx.x * 32 + w;
    if (i >= N) return;

    hs[w][j] = d_h[i * H + j];
    __syncwarp();

    float acc = bn[j];
#pragma unroll
    for (int k = 0; k < H; k++) acc += hs[w][k] * Ws[k * H + j];
#pragma unroll
    for (int k = 0; k < H; k++) acc += gs[k] * Ws[(H + k) * H + j];
    float u = fmaxf(acc, 0.f);
    d_h[i * H + j] = u;

    float v0 = u * __ldg(&Wout[j * 2]);
    float v1 = u * __ldg(&Wout[j * 2 + 1]);
#pragma unroll
    for (int off = 16; off; off >>= 1) {
        v0 += __shfl_xor_sync(0xffffffffu, v0, off);
        v1 += __shfl_xor_sync(0xffffffffu, v1, off);
    }
    float nv0 = __ldg(&V[i * 2])     + v0 + __ldg(&bout[0]);
    float nv1 = __ldg(&V[i * 2 + 1]) + v1 + __ldg(&bout[1]);
    if (j == 0) { V[i * 2] = nv0; V[i * 2 + 1] = nv1; }

    if (WmsgNext) {
        __syncwarp();
        hs[w][j] = u;
        __syncwarp();
        float t = nv0 * Wm[j] + nv1 * Wm[H + j];
#pragma unroll
        for (int k = 0; k < H; k++) t += hs[w][k] * Wm[(2 + k) * H + j];
        d_Th[i * H + j] = __float2half_rn(t);
    }
}

// ---------------------------------------------------------------------------
extern "C" void kernel_launch(void* const* d_in, const int* in_sizes, int n_in,
                              void* d_out, int out_size) {
    const float* PQ        = (const float*)d_in[0];
    const int*   senders   = (const int*)  d_in[1];
    const int*   receivers = (const int*)  d_in[2];
    const float* ef        = (const float*)d_in[3];
    const float* mask      = (const float*)d_in[4];
    const float* Win       = (const float*)d_in[5];
    const float* bin       = (const float*)d_in[6];
    const float* Wmsg      = (const float*)d_in[7];
    const float* bmsg      = (const float*)d_in[8];
    const float* Wg        = (const float*)d_in[9];
    const float* bg        = (const float*)d_in[10];
    const float* Wn        = (const float*)d_in[11];
    const float* bn        = (const float*)d_in[12];
    const float* Wout      = (const float*)d_in[13];
    const float* bout      = (const float*)d_in[14];
    float* V = (float*)d_out;

    int N = in_sizes[0] / 2;
    int E = in_sizes[1];

    int nb_nh = (N * H + 255) / 256;
    int nb_e  = (E + 255) / 256;
    int nb_sc = (N + 1023) / 1024;
    int nb_n32 = (N + 31) / 32;

    init_kernel<<<nb_nh, 256>>>(PQ, Win, bin, Wmsg, V, N);
    hist_kernel<<<nb_e, 256>>>(receivers, E);
    scan1_kernel<<<nb_sc, 1024>>>(N);
    scan2_kernel<<<1, 1024>>>(nb_sc);
    scan3_kernel<<<(N + 255) / 256, 256>>>(N);
    scatter_kernel<<<nb_e, 256>>>(senders, receivers, ef, mask, E);

    const int NB_AGG = 1480;   // 10 blocks/SM class grid; 8 warps each
    for (int l = 0; l < NL; l++) {
        agg_kernel<<<NB_AGG, 256>>>(Wmsg + l * 38 * H, bmsg + l * H,
                                    Wg + l * 2 * H * H, bg + l * H,
                                    1.0f / (float)N, N, NB_AGG * 8, NB_AGG);
        const float* WmsgNext = (l + 1 < NL) ? (Wmsg + (l + 1) * 38 * H) : nullptr;
        node_kernel<<<nb_n32, 1024>>>(Wn + l * 2 * H * H, bn + l * H,
                                      Wout + l * H * 2, bout + l * 2,
                                      WmsgNext, V, N);
    }
}

// round 11
// speedup vs baseline: 1.1706x; 1.1706x over previous
#include <cuda_runtime.h>
#include <cuda_fp16.h>

#define H    32
#define NMAX 100000
#define EMAX 3200000
#define PMAX (EMAX + 4 * NMAX)
#define NL   3

// ---- scratch (static; no allocation allowed) ----
__device__ __half d_Th[NMAX * H];      // T = node_in @ W_msg[:34]  (fp16)
__device__ float  d_h[NMAX * H];       // hidden state
__device__ float  d_pool[H];           // column sums of h
__device__ float  d_g[H];              // global supernode state
__device__ int    d_cnt[NMAX];         // degree -> scatter cursor
__device__ int    d_tmp[NMAX];         // block-local inclusive scan (padded)
__device__ int    d_rowptr[NMAX + 1];  // padded CSR row pointers (by receiver)
__device__ int    d_bsum[1024];
__device__ int    d_boff[1024];
__device__ __align__(16) float2 d_pay[PMAX];  // {sender_bits, mask}; pad slots stay 0
__device__ float4 d_aef[NMAX];         // sum mask*EF per receiver
__device__ unsigned d_ticket;          // last-block-done counter

// ---------------------------------------------------------------------------
// init: V=(1,0) ; h = PQ @ W_in + b_in ; T0 = [1,0,h] @ W_msg[0][:34]
// ---------------------------------------------------------------------------
__global__ void init_kernel(const float* __restrict__ PQ,
                            const float* __restrict__ Win,
                            const float* __restrict__ bin,
                            const float* __restrict__ Wmsg0,
                            float* __restrict__ V, int N) {
    __shared__ float Ws[34 * H];
    __shared__ float hs[8][H];
    for (int t = threadIdx.x; t < 34 * H; t += blockDim.x) Ws[t] = Wmsg0[t];

    int gid = blockIdx.x * blockDim.x + threadIdx.x;
    if (gid < H) { d_g[gid] = 0.f; d_pool[gid] = 0.f; }
    if (gid == 0) d_ticket = 0u;
    if (gid < N) {
        d_cnt[gid] = 0;
        d_aef[gid] = make_float4(0.f, 0.f, 0.f, 0.f);
    }
    if (gid < N * 2) V[gid] = (gid & 1) ? 0.f : 1.f;

    bool active = gid < N * H;
    int i = gid >> 5, j = gid & 31, w = threadIdx.x >> 5;
    float h = 0.f;
    if (active) {
        float p = __ldg(&PQ[i * 2]);
        float q = __ldg(&PQ[i * 2 + 1]);
        h = p * __ldg(&Win[j]) + q * __ldg(&Win[H + j]) + __ldg(&bin[j]);
        hs[w][j] = h;
    }
    __syncthreads();
    if (active) {
        d_h[gid] = h;
        float acc = Ws[j];                 // V = (1, 0)
#pragma unroll
        for (int k = 0; k < H; k++) acc += hs[w][k] * Ws[(2 + k) * H + j];
        d_Th[gid] = __float2half_rn(acc);
    }
}

// ---------------------------------------------------------------------------
// CSR build: histogram -> scan (padded to 4) -> scatter(+AEF)
// ---------------------------------------------------------------------------
__global__ void hist_kernel(const int* __restrict__ recv, int E) {
    int e = blockIdx.x * blockDim.x + threadIdx.x;
    if (e < E) atomicAdd(&d_cnt[__ldg(&recv[e])], 1);
}

__global__ void scan1_kernel(int N) {
    __shared__ int ws[32];
    int tid = threadIdx.x, lane = tid & 31, wid = tid >> 5;
    int i = blockIdx.x * 1024 + tid;
    int v = (i < N) ? ((d_cnt[i] + 3) & ~3) : 0;   // padded degree
    int s = v;
#pragma unroll
    for (int off = 1; off < 32; off <<= 1) {
        int n = __shfl_up_sync(0xffffffffu, s, off);
        if (lane >= off) s += n;
    }
    if (lane == 31) ws[wid] = s;
    __syncthreads();
    if (wid == 0) {
        int t = ws[lane];
#pragma unroll
        for (int off = 1; off < 32; off <<= 1) {
            int n = __shfl_up_sync(0xffffffffu, t, off);
            if (lane >= off) t += n;
        }
        ws[lane] = t;
    }
    __syncthreads();
    if (wid > 0) s += ws[wid - 1];
    if (i < N) d_tmp[i] = s;
    if (tid == 1023) d_bsum[blockIdx.x] = s;
}

__global__ void scan2_kernel(int nb) {
    __shared__ int ws[32];
    int tid = threadIdx.x, lane = tid & 31, wid = tid >> 5;
    int v = (tid < nb) ? d_bsum[tid] : 0;
    int s = v;
#pragma unroll
    for (int off = 1; off < 32; off <<= 1) {
        int n = __shfl_up_sync(0xffffffffu, s, off);
        if (lane >= off) s += n;
    }
    if (lane == 31) ws[wid] = s;
    __syncthreads();
    if (wid == 0) {
        int t = ws[lane];
#pragma unroll
        for (int off = 1; off < 32; off <<= 1) {
            int n = __shfl_up_sync(0xffffffffu, t, off);
            if (lane >= off) t += n;
        }
        ws[lane] = t;
    }
    __syncthreads();
    if (wid > 0) s += ws[wid - 1];
    d_boff[tid] = s - v;   // exclusive
}

__global__ void scan3_kernel(int N) {
    int i = blockIdx.x * blockDim.x + threadIdx.x;
    if (i == 0) d_rowptr[0] = 0;
    if (i >= N) return;
    int real = d_cnt[i];
    int pad  = (real + 3) & ~3;
    int incl = d_tmp[i] + d_boff[i >> 10];  // inclusive padded prefix
    d_rowptr[i + 1] = incl;
    d_cnt[i] = incl - pad;                  // start cursor
}

__global__ void scatter_kernel(const int*   __restrict__ send,
                               const int*   __restrict__ recv,
                               const float* __restrict__ ef,
                               const float* __restrict__ mask, int E) {
    int e = blockIdx.x * blockDim.x + threadIdx.x;
    if (e >= E) return;
    int r = __ldg(&recv[e]);
    int pos = atomicAdd(&d_cnt[r], 1);
    float mk = __ldg(&mask[e]);
    d_pay[pos] = make_float2(__int_as_float(__ldg(&send[e])), mk);
    float4 f = __ldg((const float4*)ef + e);
    float4* dst = &d_aef[r];
    asm volatile("red.global.add.v4.f32 [%0], {%1,%2,%3,%4};"
                 :: "l"(dst), "f"(mk * f.x), "f"(mk * f.y),
                    "f"(mk * f.z), "f"(mk * f.w) : "memory");
}

// ---------------------------------------------------------------------------
// agg: h[r] = relu( sum mask*T[s] + AEF[r]@W_ef + (sum mask)*b ) ; pool colsums;
// last block computes g = relu([g, pool/N] @ Wg + bg), resets pool/ticket.
// R7 shape: 4 nodes/warp, 8 lanes (4 cols) per node, 4 edges per iteration.
// cnt = sum mask accumulates per-lane for free (identical across the 8 lanes).
// ---------------------------------------------------------------------------
__global__ void __launch_bounds__(256)
agg_kernel(const float* __restrict__ Wmsg, const float* __restrict__ bmsg,
           const float* __restrict__ Wg, const float* __restrict__ bg,
           float invN, int N, int numBlocks) {
    __shared__ float4 wsum[8][8];
    __shared__ float  gin[2 * H];
    __shared__ bool   sLast;

    int lane = threadIdx.x & 31;
    int warp = threadIdx.x >> 5;
    int sub  = lane >> 3;
    int col  = (lane & 7) * 4;
    int node = blockIdx.x * 32 + warp * 4 + sub;

    float4 w0 = *(const float4*)&Wmsg[34 * H + col];
    float4 w1 = *(const float4*)&Wmsg[35 * H + col];
    float4 w2 = *(const float4*)&Wmsg[36 * H + col];
    float4 w3 = *(const float4*)&Wmsg[37 * H + col];
    float4 bb = *(const float4*)&bmsg[col];

    float4 acc = make_float4(0.f, 0.f, 0.f, 0.f);
    if (node < N) {
        int beg = __ldg(&d_rowptr[node]), end = __ldg(&d_rowptr[node + 1]);
        float cnt = 0.f;
        for (int k = beg; k < end; k += 4) {
            float4 pA = *(const float4*)&d_pay[k];      // edges k, k+1
            float4 pB = *(const float4*)&d_pay[k + 2];  // edges k+2, k+3
            uint2 r0 = *(const uint2*)(d_Th + __float_as_int(pA.x) * H + col);
            uint2 r1 = *(const uint2*)(d_Th + __float_as_int(pA.z) * H + col);
            uint2 r2 = *(const uint2*)(d_Th + __float_as_int(pB.x) * H + col);
            uint2 r3 = *(const uint2*)(d_Th + __float_as_int(pB.z) * H + col);
            float2 l0 = __half22float2(*(__half2*)&r0.x), u0 = __half22float2(*(__half2*)&r0.y);
            float2 l1 = __half22float2(*(__half2*)&r1.x), u1 = __half22float2(*(__half2*)&r1.y);
            float2 l2 = __half22float2(*(__half2*)&r2.x), u2 = __half22float2(*(__half2*)&r2.y);
            float2 l3 = __half22float2(*(__half2*)&r3.x), u3 = __half22float2(*(__half2*)&r3.y);
            acc.x = fmaf(pA.y, l0.x, acc.x); acc.y = fmaf(pA.y, l0.y, acc.y);
            acc.z = fmaf(pA.y, u0.x, acc.z); acc.w = fmaf(pA.y, u0.y, acc.w);
            acc.x = fmaf(pA.w, l1.x, acc.x); acc.y = fmaf(pA.w, l1.y, acc.y);
            acc.z = fmaf(pA.w, u1.x, acc.z); acc.w = fmaf(pA.w, u1.y, acc.w);
            acc.x = fmaf(pB.y, l2.x, acc.x); acc.y = fmaf(pB.y, l2.y, acc.y);
            acc.z = fmaf(pB.y, u2.x, acc.z); acc.w = fmaf(pB.y, u2.y, acc.w);
            acc.x = fmaf(pB.w, l3.x, acc.x); acc.y = fmaf(pB.w, l3.y, acc.y);
            acc.z = fmaf(pB.w, u3.x, acc.z); acc.w = fmaf(pB.w, u3.y, acc.w);
            cnt += pA.y + pA.w + pB.y + pB.w;   // identical across the 8 lanes
        }
        float4 aef = d_aef[node];
        acc.x += aef.x * w0.x + aef.y * w1.x + aef.z * w2.x + aef.w * w3.x + cnt * bb.x;
        acc.y += aef.x * w0.y + aef.y * w1.y + aef.z * w2.y + aef.w * w3.y + cnt * bb.y;
        acc.z += aef.x * w0.z + aef.y * w1.z + aef.z * w2.z + aef.w * w3.z + cnt * bb.z;
        acc.w += aef.x * w0.w + aef.y * w1.w + aef.z * w2.w + aef.w * w3.w + cnt * bb.w;
        acc.x = fmaxf(acc.x, 0.f); acc.y = fmaxf(acc.y, 0.f);
        acc.z = fmaxf(acc.z, 0.f); acc.w = fmaxf(acc.w, 0.f);
        *(float4*)&d_h[node * H + col] = acc;
    } else {
        acc = make_float4(0.f, 0.f, 0.f, 0.f);
    }

    // pool: sum h columns over the block's 32 nodes
#pragma unroll
    for (int off = 8; off <= 16; off <<= 1) {
        acc.x += __shfl_xor_sync(0xffffffffu, acc.x, off);
        acc.y += __shfl_xor_sync(0xffffffffu, acc.y, off);
        acc.z += __shfl_xor_sync(0xffffffffu, acc.z, off);
        acc.w += __shfl_xor_sync(0xffffffffu, acc.w, off);
    }
    if (lane < 8) wsum[warp][lane] = acc;
    __syncthreads();
    if (threadIdx.x < 8) {
        float4 s = make_float4(0.f, 0.f, 0.f, 0.f);
#pragma unroll
        for (int w = 0; w < 8; w++) {
            float4 v = wsum[w][threadIdx.x];
            s.x += v.x; s.y += v.y; s.z += v.z; s.w += v.w;
        }
        float* dst = &d_pool[threadIdx.x * 4];
        asm volatile("red.global.add.v4.f32 [%0], {%1,%2,%3,%4};"
                     :: "l"(dst), "f"(s.x), "f"(s.y), "f"(s.z), "f"(s.w) : "memory");
        __threadfence();   // writer-side: pool red visible before ticket
    }
    __syncthreads();
    if (threadIdx.x == 0) {
        unsigned t = atomicAdd(&d_ticket, 1u);
        sLast = (t == (unsigned)(numBlocks - 1));
    }
    __syncthreads();
    if (sLast && threadIdx.x < H) {
        __threadfence();   // reader-side: all pool reds now visible
        int t = threadIdx.x;
        gin[t]     = d_g[t];
        gin[H + t] = d_pool[t] * invN;
        __syncwarp();
        float a = __ldg(&bg[t]);
#pragma unroll
        for (int k = 0; k < 2 * H; k++) a += gin[k] * __ldg(&Wg[k * H + t]);
        d_g[t]    = fmaxf(a, 0.f);
        d_pool[t] = 0.f;
        if (t == 0) d_ticket = 0u;
    }
}

// ---------------------------------------------------------------------------
// node update: u = relu([h, g] @ W_n + b_n) ; V += u @ W_out + b_out ; h = u ;
// then T_next = [Vnew, u] @ W_msg[l+1][:34]   (fused next-layer prep)
// ---------------------------------------------------------------------------
__global__ void __launch_bounds__(1024)
node_kernel(const float* __restrict__ Wn, const float* __restrict__ bn,
            const float* __restrict__ Wout, const float* __restrict__ bout,
            const float* __restrict__ WmsgNext,   // nullptr on last layer
            float* __restrict__ V, int N) {
    __shared__ float Ws[2 * H * H];
    __shared__ float Wm[34 * H];
    __shared__ float gs[H];
    __shared__ float hs[32][H];
    for (int t = threadIdx.x; t < 2 * H * H; t += blockDim.x) Ws[t] = Wn[t];
    if (WmsgNext)
        for (int t = threadIdx.x; t < 34 * H; t += blockDim.x) Wm[t] = WmsgNext[t];
    if (threadIdx.x < H) gs[threadIdx.x] = d_g[threadIdx.x];
    __syncthreads();

    int w = threadIdx.x >> 5, j = threadIdx.x & 31;
    int i = blockIdx.x * 32 + w;
    if (i >= N) return;

    hs[w][j] = d_h[i * H + j];
    __syncwarp();

    float acc = bn[j];
#pragma unroll
    for (int k = 0; k < H; k++) acc += hs[w][k] * Ws[k * H + j];
#pragma unroll
    for (int k = 0; k < H; k++) acc += gs[k] * Ws[(H + k) * H + j];
    float u = fmaxf(acc, 0.f);
    d_h[i * H + j] = u;

    float v0 = u * __ldg(&Wout[j * 2]);
    float v1 = u * __ldg(&Wout[j * 2 + 1]);
#pragma unroll
    for (int off = 16; off; off >>= 1) {
        v0 += __shfl_xor_sync(0xffffffffu, v0, off);
        v1 += __shfl_xor_sync(0xffffffffu, v1, off);
    }
    float nv0 = __ldg(&V[i * 2])     + v0 + __ldg(&bout[0]);
    float nv1 = __ldg(&V[i * 2 + 1]) + v1 + __ldg(&bout[1]);
    if (j == 0) { V[i * 2] = nv0; V[i * 2 + 1] = nv1; }

    if (WmsgNext) {
        __syncwarp();
        hs[w][j] = u;
        __syncwarp();
        float t = nv0 * Wm[j] + nv1 * Wm[H + j];
#pragma unroll
        for (int k = 0; k < H; k++) t += hs[w][k] * Wm[(2 + k) * H + j];
        d_Th[i * H + j] = __float2half_rn(t);
    }
}

// ---------------------------------------------------------------------------
extern "C" void kernel_launch(void* const* d_in, const int* in_sizes, int n_in,
                              void* d_out, int out_size) {
    const float* PQ        = (const float*)d_in[0];
    const int*   senders   = (const int*)  d_in[1];
    const int*   receivers = (const int*)  d_in[2];
    const float* ef        = (const float*)d_in[3];
    const float* mask      = (const float*)d_in[4];
    const float* Win       = (const float*)d_in[5];
    const float* bin       = (const float*)d_in[6];
    const float* Wmsg      = (const float*)d_in[7];
    const float* bmsg      = (const float*)d_in[8];
    const float* Wg        = (const float*)d_in[9];
    const float* bg        = (const float*)d_in[10];
    const float* Wn        = (const float*)d_in[11];
    const float* bn        = (const float*)d_in[12];
    const float* Wout      = (const float*)d_in[13];
    const float* bout      = (const float*)d_in[14];
    float* V = (float*)d_out;

    int N = in_sizes[0] / 2;
    int E = in_sizes[1];

    int nb_nh = (N * H + 255) / 256;
    int nb_e  = (E + 255) / 256;
    int nb_sc = (N + 1023) / 1024;
    int nb_n32 = (N + 31) / 32;

    init_kernel<<<nb_nh, 256>>>(PQ, Win, bin, Wmsg, V, N);
    hist_kernel<<<nb_e, 256>>>(receivers, E);
    scan1_kernel<<<nb_sc, 1024>>>(N);
    scan2_kernel<<<1, 1024>>>(nb_sc);
    scan3_kernel<<<(N + 255) / 256, 256>>>(N);
    scatter_kernel<<<nb_e, 256>>>(senders, receivers, ef, mask, E);

    for (int l = 0; l < NL; l++) {
        agg_kernel<<<nb_n32, 256>>>(Wmsg + l * 38 * H, bmsg + l * H,
                                    Wg + l * 2 * H * H, bg + l * H,
                                    1.0f / (float)N, N, nb_n32);
        const float* WmsgNext = (l + 1 < NL) ? (Wmsg + (l + 1) * 38 * H) : nullptr;
        node_kernel<<<nb_n32, 1024>>>(Wn + l * 2 * H * H, bn + l * H,
                                      Wout + l * H * 2, bout + l * 2,
                                      WmsgNext, V, N);
    }
}

// round 13
// speedup vs baseline: 1.2624x; 1.0784x over previous
#include <cuda_runtime.h>
#include <cuda_fp16.h>

#define H    32
#define NMAX 100000
#define EMAX 3200000
#define PMAX (EMAX + 4 * NMAX)
#define NL   3

// ---- scratch (static; no allocation allowed) ----
__device__ __half d_Th[NMAX * H];      // T = node_in @ W_msg[:34]  (fp16)
__device__ float  d_h[NMAX * H];       // hidden state
__device__ float  d_pool[H];           // column sums of h
__device__ float  d_g[H];              // global supernode state
__device__ int    d_cnt[NMAX];         // degree -> scatter cursor
__device__ int    d_tmp[NMAX];         // block-local inclusive scan (padded)
__device__ int    d_rowptr[NMAX + 1];  // padded CSR row pointers (by receiver)
__device__ int    d_bsum[1024];
__device__ int    d_boff[1024];
__device__ __align__(16) float2 d_pay[PMAX];  // {sender_bits, mask}; pad slots stay 0
__device__ float4 d_aef[NMAX];         // sum mask*EF per receiver

// ---------------------------------------------------------------------------
// init: V=(1,0) ; h = PQ @ W_in + b_in ; T0 = [1,0,h] @ W_msg[0][:34]
// ---------------------------------------------------------------------------
__global__ void init_kernel(const float* __restrict__ PQ,
                            const float* __restrict__ Win,
                            const float* __restrict__ bin,
                            const float* __restrict__ Wmsg0,
                            float* __restrict__ V, int N) {
    __shared__ float Ws[34 * H];
    __shared__ float hs[8][H];
    for (int t = threadIdx.x; t < 34 * H; t += blockDim.x) Ws[t] = Wmsg0[t];

    int gid = blockIdx.x * blockDim.x + threadIdx.x;
    if (gid < H) { d_g[gid] = 0.f; d_pool[gid] = 0.f; }
    if (gid < N) {
        d_cnt[gid] = 0;
        d_aef[gid] = make_float4(0.f, 0.f, 0.f, 0.f);
    }
    if (gid < N * 2) V[gid] = (gid & 1) ? 0.f : 1.f;

    bool active = gid < N * H;
    int i = gid >> 5, j = gid & 31, w = threadIdx.x >> 5;
    float h = 0.f;
    if (active) {
        float p = __ldg(&PQ[i * 2]);
        float q = __ldg(&PQ[i * 2 + 1]);
        h = p * __ldg(&Win[j]) + q * __ldg(&Win[H + j]) + __ldg(&bin[j]);
        hs[w][j] = h;
    }
    __syncthreads();
    if (active) {
        d_h[gid] = h;
        float acc = Ws[j];                 // V = (1, 0)
#pragma unroll
        for (int k = 0; k < H; k++) acc += hs[w][k] * Ws[(2 + k) * H + j];
        d_Th[gid] = __float2half_rn(acc);
    }
}

// ---------------------------------------------------------------------------
// CSR build: histogram -> scan (padded to 4) -> scatter(+AEF)
// ---------------------------------------------------------------------------
__global__ void hist_kernel(const int* __restrict__ recv, int E) {
    int e = blockIdx.x * blockDim.x + threadIdx.x;
    if (e < E) atomicAdd(&d_cnt[__ldg(&recv[e])], 1);
}

__global__ void scan1_kernel(int N) {
    __shared__ int ws[32];
    int tid = threadIdx.x, lane = tid & 31, wid = tid >> 5;
    int i = blockIdx.x * 1024 + tid;
    int v = (i < N) ? ((d_cnt[i] + 3) & ~3) : 0;   // padded degree
    int s = v;
#pragma unroll
    for (int off = 1; off < 32; off <<= 1) {
        int n = __shfl_up_sync(0xffffffffu, s, off);
        if (lane >= off) s += n;
    }
    if (lane == 31) ws[wid] = s;
    __syncthreads();
    if (wid == 0) {
        int t = ws[lane];
#pragma unroll
        for (int off = 1; off < 32; off <<= 1) {
            int n = __shfl_up_sync(0xffffffffu, t, off);
            if (lane >= off) t += n;
        }
        ws[lane] = t;
    }
    __syncthreads();
    if (wid > 0) s += ws[wid - 1];
    if (i < N) d_tmp[i] = s;
    if (tid == 1023) d_bsum[blockIdx.x] = s;
}

__global__ void scan2_kernel(int nb) {
    __shared__ int ws[32];
    int tid = threadIdx.x, lane = tid & 31, wid = tid >> 5;
    int v = (tid < nb) ? d_bsum[tid] : 0;
    int s = v;
#pragma unroll
    for (int off = 1; off < 32; off <<= 1) {
        int n = __shfl_up_sync(0xffffffffu, s, off);
        if (lane >= off) s += n;
    }
    if (lane == 31) ws[wid] = s;
    __syncthreads();
    if (wid == 0) {
        int t = ws[lane];
#pragma unroll
        for (int off = 1; off < 32; off <<= 1) {
            int n = __shfl_up_sync(0xffffffffu, t, off);
            if (lane >= off) t += n;
        }
        ws[lane] = t;
    }
    __syncthreads();
    if (wid > 0) s += ws[wid - 1];
    d_boff[tid] = s - v;   // exclusive
}

__global__ void scan3_kernel(int N) {
    int i = blockIdx.x * blockDim.x + threadIdx.x;
    if (i == 0) d_rowptr[0] = 0;
    if (i >= N) return;
    int real = d_cnt[i];
    int pad  = (real + 3) & ~3;
    int incl = d_tmp[i] + d_boff[i >> 10];  // inclusive padded prefix
    d_rowptr[i + 1] = incl;
    d_cnt[i] = incl - pad;                  // start cursor
}

__global__ void scatter_kernel(const int*   __restrict__ send,
                               const int*   __restrict__ recv,
                               const float* __restrict__ ef,
                               const float* __restrict__ mask, int E) {
    int e = blockIdx.x * blockDim.x + threadIdx.x;
    if (e >= E) return;
    int r = __ldg(&recv[e]);
    int pos = atomicAdd(&d_cnt[r], 1);
    float mk = __ldg(&mask[e]);
    d_pay[pos] = make_float2(__int_as_float(__ldg(&send[e])), mk);
    float4 f = __ldg((const float4*)ef + e);
    float4* dst = &d_aef[r];
    asm volatile("red.global.add.v4.f32 [%0], {%1,%2,%3,%4};"
                 :: "l"(dst), "f"(mk * f.x), "f"(mk * f.y),
                    "f"(mk * f.z), "f"(mk * f.w) : "memory");
}

// ---------------------------------------------------------------------------
// agg: h[r] = relu( sum mask*T[s] + AEF[r]@W_ef + (sum mask)*b ) ; pool colsums
// 4 nodes/warp, 8 lanes (4 cols) per node. 8 edges per main-loop iteration
// (padded CSR: deg % 4 == 0, so remainder is one 4-edge step).
// ---------------------------------------------------------------------------
#define EDGE4(p0, p1)                                                          \
    {                                                                          \
        uint2 rA = *(const uint2*)(d_Th + __float_as_int((p0).x) * H + col);   \
        uint2 rB = *(const uint2*)(d_Th + __float_as_int((p0).z) * H + col);   \
        uint2 rC = *(const uint2*)(d_Th + __float_as_int((p1).x) * H + col);   \
        uint2 rD = *(const uint2*)(d_Th + __float_as_int((p1).z) * H + col);   \
        float2 lA = __half22float2(*(__half2*)&rA.x), uA = __half22float2(*(__half2*)&rA.y); \
        float2 lB = __half22float2(*(__half2*)&rB.x), uB = __half22float2(*(__half2*)&rB.y); \
        float2 lC = __half22float2(*(__half2*)&rC.x), uC = __half22float2(*(__half2*)&rC.y); \
        float2 lD = __half22float2(*(__half2*)&rD.x), uD = __half22float2(*(__half2*)&rD.y); \
        acc.x = fmaf((p0).y, lA.x, acc.x); acc.y = fmaf((p0).y, lA.y, acc.y);  \
        acc.z = fmaf((p0).y, uA.x, acc.z); acc.w = fmaf((p0).y, uA.y, acc.w);  \
        acc.x = fmaf((p0).w, lB.x, acc.x); acc.y = fmaf((p0).w, lB.y, acc.y);  \
        acc.z = fmaf((p0).w, uB.x, acc.z); acc.w = fmaf((p0).w, uB.y, acc.w);  \
        acc.x = fmaf((p1).y, lC.x, acc.x); acc.y = fmaf((p1).y, lC.y, acc.y);  \
        acc.z = fmaf((p1).y, uC.x, acc.z); acc.w = fmaf((p1).y, uC.y, acc.w);  \
        acc.x = fmaf((p1).w, lD.x, acc.x); acc.y = fmaf((p1).w, lD.y, acc.y);  \
        acc.z = fmaf((p1).w, uD.x, acc.z); acc.w = fmaf((p1).w, uD.y, acc.w);  \
        cnt += (p0).y + (p0).w + (p1).y + (p1).w;                              \
    }

__global__ void agg_kernel(const float* __restrict__ Wmsg,
                           const float* __restrict__ bmsg, int N) {
    __shared__ float4 wsum[8][8];

    int lane = threadIdx.x & 31;
    int warp = threadIdx.x >> 5;
    int sub  = lane >> 3;
    int col  = (lane & 7) * 4;
    int node = blockIdx.x * 32 + warp * 4 + sub;

    float4 w0 = *(const float4*)&Wmsg[34 * H + col];
    float4 w1 = *(const float4*)&Wmsg[35 * H + col];
    float4 w2 = *(const float4*)&Wmsg[36 * H + col];
    float4 w3 = *(const float4*)&Wmsg[37 * H + col];
    float4 bb = *(const float4*)&bmsg[col];

    float4 acc = make_float4(0.f, 0.f, 0.f, 0.f);
    if (node < N) {
        int beg = __ldg(&d_rowptr[node]), end = __ldg(&d_rowptr[node + 1]);
        float cnt = 0.f;
        int deg  = end - beg;
        int end8 = beg + (deg & ~7);
        int k = beg;
        for (; k < end8; k += 8) {       // 8 edges: 4 payload + 8 T gathers in flight
            float4 p0 = *(const float4*)&d_pay[k];
            float4 p1 = *(const float4*)&d_pay[k + 2];
            float4 p2 = *(const float4*)&d_pay[k + 4];
            float4 p3 = *(const float4*)&d_pay[k + 6];
            EDGE4(p0, p1);
            EDGE4(p2, p3);
        }
        if (k < end) {                   // remainder: exactly 4 edges
            float4 p0 = *(const float4*)&d_pay[k];
            float4 p1 = *(const float4*)&d_pay[k + 2];
            EDGE4(p0, p1);
        }
        float4 aef = d_aef[node];
        acc.x += aef.x * w0.x + aef.y * w1.x + aef.z * w2.x + aef.w * w3.x + cnt * bb.x;
        acc.y += aef.x * w0.y + aef.y * w1.y + aef.z * w2.y + aef.w * w3.y + cnt * bb.y;
        acc.z += aef.x * w0.z + aef.y * w1.z + aef.z * w2.z + aef.w * w3.z + cnt * bb.z;
        acc.w += aef.x * w0.w + aef.y * w1.w + aef.z * w2.w + aef.w * w3.w + cnt * bb.w;
        acc.x = fmaxf(acc.x, 0.f); acc.y = fmaxf(acc.y, 0.f);
        acc.z = fmaxf(acc.z, 0.f); acc.w = fmaxf(acc.w, 0.f);
        *(float4*)&d_h[node * H + col] = acc;
    } else {
        acc = make_float4(0.f, 0.f, 0.f, 0.f);
    }

    // pool: sum h columns over the block's 32 nodes
#pragma unroll
    for (int off = 8; off <= 16; off <<= 1) {
        acc.x += __shfl_xor_sync(0xffffffffu, acc.x, off);
        acc.y += __shfl_xor_sync(0xffffffffu, acc.y, off);
        acc.z += __shfl_xor_sync(0xffffffffu, acc.z, off);
        acc.w += __shfl_xor_sync(0xffffffffu, acc.w, off);
    }
    if (lane < 8) wsum[warp][lane] = acc;
    __syncthreads();
    if (threadIdx.x < 8) {
        float4 s = make_float4(0.f, 0.f, 0.f, 0.f);
#pragma unroll
        for (int w = 0; w < 8; w++) {
            float4 v = wsum[w][threadIdx.x];
            s.x += v.x; s.y += v.y; s.z += v.z; s.w += v.w;
        }
        float* dst = &d_pool[threadIdx.x * 4];
        asm volatile("red.global.add.v4.f32 [%0], {%1,%2,%3,%4};"
                     :: "l"(dst), "f"(s.x), "f"(s.y), "f"(s.z), "f"(s.w) : "memory");
    }
}

// ---------------------------------------------------------------------------
// global node: g = relu([g, mean(h)] @ W_g + b_g) ; reset pool for next layer
// ---------------------------------------------------------------------------
__global__ void g_kernel(const float* __restrict__ Wg,
                         const float* __restrict__ bg, float invN) {
    __shared__ float gin[2 * H];
    int t = threadIdx.x;
    gin[t]     = d_g[t];
    gin[H + t] = d_pool[t] * invN;
    d_pool[t]  = 0.f;
    __syncthreads();
    float acc = bg[t];
#pragma unroll
    for (int k = 0; k < 2 * H; k++) acc += gin[k] * Wg[k * H + t];
    d_g[t] = fmaxf(acc, 0.f);
}

// ---------------------------------------------------------------------------
// node update: u = relu([h, g] @ W_n + b_n) ; V += u @ W_out + b_out ; h = u ;
// then T_next = [Vnew, u] @ W_msg[l+1][:34]   (fused next-layer prep)
// ---------------------------------------------------------------------------
__global__ void __launch_bounds__(1024)
node_kernel(const float* __restrict__ Wn, const float* __restrict__ bn,
            const float* __restrict__ Wout, const float* __restrict__ bout,
            const float* __restrict__ WmsgNext,   // nullptr on last layer
            float* __restrict__ V, int N) {
    __shared__ float Ws[2 * H * H];
    __shared__ float Wm[34 * H];
    __shared__ float gs[H];
    __shared__ float hs[32][H];
    for (int t = threadIdx.x; t < 2 * H * H; t += blockDim.x) Ws[t] = Wn[t];
    if (WmsgNext)
        for (int t = threadIdx.x; t < 34 * H; t += blockDim.x) Wm[t] = WmsgNext[t];
    if (threadIdx.x < H) gs[threadIdx.x] = d_g[threadIdx.x];
    __syncthreads();

    int w = threadIdx.x >> 5, j = threadIdx.x & 31;
    int i = blockIdx.x * 32 + w;
    if (i >= N) return;

    hs[w][j] = d_h[i * H + j];
    __syncwarp();

    float acc = bn[j];
#pragma unroll
    for (int k = 0; k < H; k++) acc += hs[w][k] * Ws[k * H + j];
#pragma unroll
    for (int k = 0; k < H; k++) acc += gs[k] * Ws[(H + k) * H + j];
    float u = fmaxf(acc, 0.f);
    d_h[i * H + j] = u;

    float v0 = u * __ldg(&Wout[j * 2]);
    float v1 = u * __ldg(&Wout[j * 2 + 1]);
#pragma unroll
    for (int off = 16; off; off >>= 1) {
        v0 += __shfl_xor_sync(0xffffffffu, v0, off);
        v1 += __shfl_xor_sync(0xffffffffu, v1, off);
    }
    float nv0 = __ldg(&V[i * 2])     + v0 + __ldg(&bout[0]);
    float nv1 = __ldg(&V[i * 2 + 1]) + v1 + __ldg(&bout[1]);
    if (j == 0) { V[i * 2] = nv0; V[i * 2 + 1] = nv1; }

    if (WmsgNext) {
        __syncwarp();
        hs[w][j] = u;
        __syncwarp();
        float t = nv0 * Wm[j] + nv1 * Wm[H + j];
#pragma unroll
        for (int k = 0; k < H; k++) t += hs[w][k] * Wm[(2 + k) * H + j];
        d_Th[i * H + j] = __float2half_rn(t);
    }
}

// ---------------------------------------------------------------------------
extern "C" void kernel_launch(void* const* d_in, const int* in_sizes, int n_in,
                              void* d_out, int out_size) {
    const float* PQ        = (const float*)d_in[0];
    const int*   senders   = (const int*)  d_in[1];
    const int*   receivers = (const int*)  d_in[2];
    const float* ef        = (const float*)d_in[3];
    const float* mask      = (const float*)d_in[4];
    const float* Win       = (const float*)d_in[5];
    const float* bin       = (const float*)d_in[6];
    const float* Wmsg      = (const float*)d_in[7];
    const float* bmsg      = (const float*)d_in[8];
    const float* Wg        = (const float*)d_in[9];
    const float* bg        = (const float*)d_in[10];
    const float* Wn        = (const float*)d_in[11];
    const float* bn        = (const float*)d_in[12];
    const float* Wout      = (const float*)d_in[13];
    const float* bout      = (const float*)d_in[14];
    float* V = (float*)d_out;

    int N = in_sizes[0] / 2;
    int E = in_sizes[1];

    int nb_nh = (N * H + 255) / 256;
    int nb_e  = (E + 255) / 256;
    int nb_sc = (N + 1023) / 1024;
    int nb_n32 = (N + 31) / 32;

    init_kernel<<<nb_nh, 256>>>(PQ, Win, bin, Wmsg, V, N);
    hist_kernel<<<nb_e, 256>>>(receivers, E);
    scan1_kernel<<<nb_sc, 1024>>>(N);
    scan2_kernel<<<1, 1024>>>(nb_sc);
    scan3_kernel<<<(N + 255) / 256, 256>>>(N);
    scatter_kernel<<<nb_e, 256>>>(senders, receivers, ef, mask, E);

    for (int l = 0; l < NL; l++) {
        agg_kernel<<<nb_n32, 256>>>(Wmsg + l * 38 * H, bmsg + l * H, N);
        g_kernel<<<1, 32>>>(Wg + l * 2 * H * H, bg + l * H, 1.0f / (float)N);
        const float* WmsgNext = (l + 1 < NL) ? (Wmsg + (l + 1) * 38 * H) : nullptr;
        node_kernel<<<nb_n32, 1024>>>(Wn + l * 2 * H * H, bn + l * H,
                                      Wout + l * H * 2, bout + l * 2,
                                      WmsgNext, V, N);
    }
}